// round 1
// baseline (speedup 1.0000x reference)
#include <cuda_runtime.h>

// Problem constants (fixed by setup_inputs)
#define B_ 16
#define A_ 9
#define H_ 128
#define W_ 128
#define S_ 2048.0f
#define THRESH_ 0.7f

// Precomputed anchor table: for each (a, w), the 4 params (acx, acy, aw, ah).
// 9*128*4 floats = 18 KB — stays resident in L1/L2 during the main kernel.
__device__ float4 d_anc_tab[A_ * W_];

__global__ void build_anchor_tab(const float* __restrict__ anchor) {
    int t = blockIdx.x * blockDim.x + threadIdx.x;
    if (t >= A_ * W_) return;
    int a = t / W_;
    int w = t % W_;
    // idx[a, w] = (w*W + w) * a = a * w * (W+1)
    long row = (long)a * w * (W_ + 1);
    const float* p = anchor + row * 6;
    d_anc_tab[t] = make_float4(p[2], p[3], p[4], p[5]);
}

// Each thread processes 4 consecutive w positions:
//   - 6 x LDG.128 inputs (cla0, cla1, tx, ty, tw, th)
//   - 4 x float4 anchor-table reads (L1-hot)
//   - 9 x STG.128 outputs (36 contiguous floats, 144B-aligned)
__global__ __launch_bounds__(256) void proposal_kernel(
    const float* __restrict__ cla,
    const float* __restrict__ reg,
    float* __restrict__ out)
{
    const int WQ = W_ / 4;          // 32 vec-groups per row
    const int HW = H_ * W_;         // 16384
    const int HW4 = HW / 4;         // 4096

    int t = blockIdx.x * blockDim.x + threadIdx.x;  // vec-group id
    // total vec-groups = B*A*H*WQ = 589824, grid sized exactly
    int wq = t % WQ;
    int h  = (t / WQ) % H_;
    int a  = (t / (WQ * H_)) % A_;
    int b  =  t / (WQ * H_ * A_);
    int w0 = wq * 4;

    int sp4 = (h * W_ + w0) >> 2;   // float4 index within a channel plane

    const float4* cla4 = (const float4*)cla;
    const float4* reg4 = (const float4*)reg;

    int cbase = (b * 2 * A_ + 2 * a) * HW4 + sp4;
    float4 v_c0 = cla4[cbase];
    float4 v_c1 = cla4[cbase + HW4];

    int rbase = (b * 4 * A_ + 4 * a) * HW4 + sp4;
    float4 v_tx = reg4[rbase + 0 * HW4];
    float4 v_ty = reg4[rbase + 1 * HW4];
    float4 v_tw = reg4[rbase + 2 * HW4];
    float4 v_th = reg4[rbase + 3 * HW4];

    float c0a[4] = {v_c0.x, v_c0.y, v_c0.z, v_c0.w};
    float c1a[4] = {v_c1.x, v_c1.y, v_c1.z, v_c1.w};
    float txa[4] = {v_tx.x, v_tx.y, v_tx.z, v_tx.w};
    float tya[4] = {v_ty.x, v_ty.y, v_ty.z, v_ty.w};
    float twa[4] = {v_tw.x, v_tw.y, v_tw.z, v_tw.w};
    float tha[4] = {v_th.x, v_th.y, v_th.z, v_th.w};

    float res[36];

    #pragma unroll
    for (int i = 0; i < 4; i++) {
        float4 anc = d_anc_tab[a * W_ + w0 + i];
        float acx = anc.x, acy = anc.y, aw = anc.z, ah = anc.w;

        // softmax over 2 channels, channel 1 == sigmoid(c1 - c0)
        float fg = 1.0f / (1.0f + expf(c0a[i] - c1a[i]));

        // normalized center/size (== scaled values / S, exact since S = 2^11)
        float cxn = fmaf(txa[i], aw, acx);
        float cyn = fmaf(tya[i], ah, acy);
        float wvn = expf(twa[i]) * aw;
        float hvn = expf(tha[i]) * ah;

        float cx = cxn * S_;
        float cy = cyn * S_;
        float wv = wvn * S_;
        float hv = hvn * S_;

        float ltx = cx - 0.5f * wv;
        float lty = cy - 0.5f * hv;
        float rbx = cx + 0.5f * wv;
        float rby = cy + 0.5f * hv;

        bool valid = (fg > THRESH_) && (ltx >= 0.0f) && (lty >= 0.0f)
                     && (rbx <= S_) && (rby <= S_);
        float m = valid ? 1.0f : 0.0f;

        res[i * 9 + 0] = ltx * m;
        res[i * 9 + 1] = lty * m;
        res[i * 9 + 2] = rbx * m;
        res[i * 9 + 3] = rby * m;
        res[i * 9 + 4] = cxn * m;
        res[i * 9 + 5] = cyn * m;
        res[i * 9 + 6] = wvn * m;
        res[i * 9 + 7] = hvn * m;
        res[i * 9 + 8] = m;
    }

    // Output block: 36 contiguous floats starting at a 144-byte boundary.
    size_t ob = ((((size_t)b * A_ + a) * H_ + h) * W_ + w0) * 9;
    float4* o4 = (float4*)(out + ob);
    #pragma unroll
    for (int j = 0; j < 9; j++) {
        o4[j] = make_float4(res[4 * j + 0], res[4 * j + 1],
                            res[4 * j + 2], res[4 * j + 3]);
    }
}

extern "C" void kernel_launch(void* const* d_in, const int* in_sizes, int n_in,
                              void* d_out, int out_size) {
    const float* cla    = (const float*)d_in[0];
    const float* reg    = (const float*)d_in[1];
    const float* anchor = (const float*)d_in[2];
    float* out = (float*)d_out;

    build_anchor_tab<<<(A_ * W_ + 127) / 128, 128>>>(anchor);

    int total_vec = B_ * A_ * H_ * (W_ / 4);   // 589824
    proposal_kernel<<<total_vec / 256, 256>>>(cla, reg, out);
}

// round 2
// speedup vs baseline: 1.2964x; 1.2964x over previous
#include <cuda_runtime.h>

// Problem constants (fixed by setup_inputs)
#define B_ 16
#define A_ 9
#define H_ 128
#define W_ 128
#define S_ 2048.0f
#define THRESH_ 0.7f

#define TPB 128                 // threads per block
#define PAD 37                  // smem stride per thread (gcd(37,32)=1 -> conflict-free)

// Precomputed anchor table: for each (a, w), the 4 params (acx, acy, aw, ah).
// 9*128*4 floats = 18 KB - L1/L2 resident during the main kernel.
__device__ float4 d_anc_tab[A_ * W_];

__global__ void build_anchor_tab(const float* __restrict__ anchor) {
    int t = blockIdx.x * blockDim.x + threadIdx.x;
    if (t >= A_ * W_) return;
    int a = t / W_;
    int w = t % W_;
    // idx[a, w] = (w*W + w) * a = a * w * (W+1)
    long row = (long)a * w * (W_ + 1);
    const float* p = anchor + row * 6;
    d_anc_tab[t] = make_float4(p[2], p[3], p[4], p[5]);
}

// Each thread processes 4 consecutive w positions (vectorized LDG.128 inputs),
// writes its 36 results into padded smem, then the block streams its
// contiguous output region to GMEM with fully coalesced 128B warp stores.
__global__ __launch_bounds__(TPB) void proposal_kernel(
    const float* __restrict__ cla,
    const float* __restrict__ reg,
    float* __restrict__ out)
{
    __shared__ float sm[TPB * PAD];

    const int WQ  = W_ / 4;         // 32 vec-groups per row
    const int HW4 = (H_ * W_) / 4;  // 4096 float4 per channel plane

    int tid = threadIdx.x;
    int t = blockIdx.x * TPB + tid;     // global vec-group id
    int wq = t % WQ;
    int h  = (t / WQ) % H_;
    int a  = (t / (WQ * H_)) % A_;
    int b  =  t / (WQ * H_ * A_);
    int w0 = wq * 4;

    int sp4 = (h * W_ + w0) >> 2;

    const float4* cla4 = (const float4*)cla;
    const float4* reg4 = (const float4*)reg;

    int cbase = (b * 2 * A_ + 2 * a) * HW4 + sp4;
    float4 v_c0 = cla4[cbase];
    float4 v_c1 = cla4[cbase + HW4];

    int rbase = (b * 4 * A_ + 4 * a) * HW4 + sp4;
    float4 v_tx = reg4[rbase + 0 * HW4];
    float4 v_ty = reg4[rbase + 1 * HW4];
    float4 v_tw = reg4[rbase + 2 * HW4];
    float4 v_th = reg4[rbase + 3 * HW4];

    float c0a[4] = {v_c0.x, v_c0.y, v_c0.z, v_c0.w};
    float c1a[4] = {v_c1.x, v_c1.y, v_c1.z, v_c1.w};
    float txa[4] = {v_tx.x, v_tx.y, v_tx.z, v_tx.w};
    float tya[4] = {v_ty.x, v_ty.y, v_ty.z, v_ty.w};
    float twa[4] = {v_tw.x, v_tw.y, v_tw.z, v_tw.w};
    float tha[4] = {v_th.x, v_th.y, v_th.z, v_th.w};

    float* my = sm + tid * PAD;

    #pragma unroll
    for (int i = 0; i < 4; i++) {
        float4 anc = d_anc_tab[a * W_ + w0 + i];
        float acx = anc.x, acy = anc.y, aw = anc.z, ah = anc.w;

        // softmax over 2 channels, channel 1 == sigmoid(c1 - c0)
        float fg = 1.0f / (1.0f + expf(c0a[i] - c1a[i]));

        // normalized center/size (== scaled values / S, exact since S = 2^11)
        float cxn = fmaf(txa[i], aw, acx);
        float cyn = fmaf(tya[i], ah, acy);
        float wvn = expf(twa[i]) * aw;
        float hvn = expf(tha[i]) * ah;

        float cx = cxn * S_;
        float cy = cyn * S_;
        float wv = wvn * S_;
        float hv = hvn * S_;

        float ltx = cx - 0.5f * wv;
        float lty = cy - 0.5f * hv;
        float rbx = cx + 0.5f * wv;
        float rby = cy + 0.5f * hv;

        bool valid = (fg > THRESH_) && (ltx >= 0.0f) && (lty >= 0.0f)
                     && (rbx <= S_) && (rby <= S_);
        float m = valid ? 1.0f : 0.0f;

        // Store straight to padded smem (bank stride 37 mod 32 = 5: conflict-free)
        my[i * 9 + 0] = ltx * m;
        my[i * 9 + 1] = lty * m;
        my[i * 9 + 2] = rbx * m;
        my[i * 9 + 3] = rby * m;
        my[i * 9 + 4] = cxn * m;
        my[i * 9 + 5] = cyn * m;
        my[i * 9 + 6] = wvn * m;
        my[i * 9 + 7] = hvn * m;
        my[i * 9 + 8] = m;
    }

    __syncthreads();

    // Block's output region: TPB*36 contiguous floats. Copy fully coalesced:
    // consecutive lanes -> consecutive 4B addresses (128B per warp store).
    // smem source addr = o + o/36 (stride-37 padding), near-monotone -> ~no conflicts.
    size_t base = (size_t)blockIdx.x * (TPB * 36);
    #pragma unroll
    for (int it = 0; it < 36; it++) {
        int o = tid + it * TPB;
        float v = sm[o + o / 36];
        __stcs(out + base + o, v);   // streaming store: don't pollute L2
    }
}

extern "C" void kernel_launch(void* const* d_in, const int* in_sizes, int n_in,
                              void* d_out, int out_size) {
    const float* cla    = (const float*)d_in[0];
    const float* reg    = (const float*)d_in[1];
    const float* anchor = (const float*)d_in[2];
    float* out = (float*)d_out;

    build_anchor_tab<<<(A_ * W_ + 127) / 128, 128>>>(anchor);

    int total_vec = B_ * A_ * H_ * (W_ / 4);   // 589824
    proposal_kernel<<<total_vec / TPB, TPB>>>(cla, reg, out);
}